// round 6
// baseline (speedup 1.0000x reference)
#include <cuda_runtime.h>
#include <cuda_bf16.h>

#define NQ      10
#define DIM     1024
#define LAYERS  8
#define THREADS 512

__device__ __forceinline__ int suffix_parity(int x) {
    // bit p of result = XOR of bits p..9 of x
    x ^= x >> 1;
    x ^= x >> 2;
    x ^= x >> 4;
    x ^= x >> 8;
    return x;
}

// outMode: 0 = real-part only, (128,1024) float32          (out_size 131072)
//          1 = global planar: re block then im block        (out_size 262144)
__global__ __launch_bounds__(THREADS)
void UnitaryR3Ansatz_kernel(const float* __restrict__ inp,
                            const float* __restrict__ params,
                            float* __restrict__ outF,
                            int outMode)
{
    const int b    = blockIdx.x;   // row 0..127
    const int copy = b >> 2;       // jnp.repeat(M, 4)
    const int t    = threadIdx.x;  // 0..511

    __shared__ float2 st[DIM];
    __shared__ float2 mat[NQ][4];

    st[t]       = make_float2(inp[b * DIM + t],       0.0f);
    st[t + 512] = make_float2(inp[b * DIM + t + 512], 0.0f);

    const int g0 = suffix_parity(t);
    const int g1 = suffix_parity(t + 512);
    __syncthreads();

    for (int layer = 0; layer < LAYERS; ++layer) {
        // rotation matrices for (copy, layer) — reference _r3 verbatim
        if (t < NQ) {
            const float* a = params + ((size_t)(copy * LAYERS + layer) * NQ + t) * 3;
            const float omega = a[0], theta = a[1], phi = a[2];
            float s,  c;  sincosf(0.5f * theta,         &s,  &c);
            float sp, cp; sincosf(0.5f * (phi + omega), &sp, &cp);
            float sm, cm; sincosf(0.5f * (phi - omega), &sm, &cm);
            mat[t][0] = make_float2( cp * c, -sp * c);   // m11
            mat[t][1] = make_float2(-cm * s, -sm * s);   // m12
            mat[t][2] = make_float2( cm * s, -sm * s);   // m21
            mat[t][3] = make_float2( cp * c,  sp * c);   // m22
        }
        __syncthreads();

        // 10 single-qubit rotations; qubit q acts on bit (9-q)
        #pragma unroll
        for (int q = 0; q < NQ; ++q) {
            const int bit = 1 << (9 - q);
            const int lo  = t & (bit - 1);
            const int j0  = ((t ^ lo) << 1) | lo;
            const int j1  = j0 | bit;

            const float2 a0 = st[j0];
            const float2 a1 = st[j1];
            const float2 m11 = mat[q][0], m12 = mat[q][1];
            const float2 m21 = mat[q][2], m22 = mat[q][3];

            float2 r0, r1;
            r0.x = m11.x*a0.x - m11.y*a0.y + m12.x*a1.x - m12.y*a1.y;
            r0.y = m11.x*a0.y + m11.y*a0.x + m12.x*a1.y + m12.y*a1.x;
            r1.x = m21.x*a0.x - m21.y*a0.y + m22.x*a1.x - m22.y*a1.y;
            r1.y = m21.x*a0.y + m21.y*a0.x + m22.x*a1.y + m22.y*a1.x;

            st[j0] = r0;
            st[j1] = r1;
            __syncthreads();
        }

        // entangling CNOT chain == static permutation gather
        const float2 e0 = st[g0];
        const float2 e1 = st[g1];
        __syncthreads();
        st[t]       = e0;
        st[t + 512] = e1;
        __syncthreads();
    }

    if (outMode == 0) {
        // real part only: float32 (128, 1024)
        outF[b * DIM + t]       = st[t].x;
        outF[b * DIM + t + 512] = st[t + 512].x;
    } else {
        // global planar: re block (128*1024 floats) then im block
        float* re = outF;
        float* im = outF + 128 * DIM;
        re[b * DIM + t]       = st[t].x;
        re[b * DIM + t + 512] = st[t + 512].x;
        im[b * DIM + t]       = st[t].y;
        im[b * DIM + t + 512] = st[t + 512].y;
    }
}

extern "C" void kernel_launch(void* const* d_in, const int* in_sizes, int n_in,
                              void* d_out, int out_size)
{
    const float* inp    = (const float*)d_in[0];
    const float* params = (const float*)d_in[1];
    if (n_in >= 2 && in_sizes[0] < in_sizes[1]) {
        inp    = (const float*)d_in[1];
        params = (const float*)d_in[0];
    }

    // out_size == 128*1024      -> harness kept only the real part (astype)
    // out_size == 2*128*1024    -> complex split into planar re/im blocks
    const int outMode = (out_size == 128 * DIM) ? 0 : 1;

    UnitaryR3Ansatz_kernel<<<128, THREADS>>>(inp, params, (float*)d_out, outMode);
}

// round 7
// speedup vs baseline: 1.5584x; 1.5584x over previous
#include <cuda_runtime.h>
#include <cuda_bf16.h>

#define NQ      10
#define DIM     1024
#define LAYERS  8
#define THREADS 256

__device__ __forceinline__ int sp10(int x) {
    // suffix parity: bit p = XOR of bits p..9   (the CNOT-chain permutation)
    x ^= x >> 1; x ^= x >> 2; x ^= x >> 4; x ^= x >> 8;
    return x;
}
__device__ __forceinline__ int padi(int j) { return j + (j >> 4); }  // bank-conflict pad

__device__ __forceinline__ float2 cfma2(float2 ca, float2 a, float2 cb, float2 b) {
    float2 r;
    r.x = ca.x*a.x - ca.y*a.y + cb.x*b.x - cb.y*b.y;
    r.y = ca.x*a.y + ca.y*a.x + cb.x*b.y + cb.y*b.x;
    return r;
}

__device__ __forceinline__ void gate_pair(float2& a0, float2& a1, const float2* m) {
    float2 n0 = cfma2(m[0], a0, m[1], a1);
    float2 n1 = cfma2(m[2], a0, m[3], a1);
    a0 = n0; a1 = n1;
}

__device__ __forceinline__ void gate_shfl(float2 v[4], int hibit, int mask, const float2* m) {
    const float2 ca = hibit ? m[3] : m[0];   // multiplies own amplitude
    const float2 cb = hibit ? m[2] : m[1];   // multiplies partner amplitude
    #pragma unroll
    for (int r = 0; r < 4; ++r) {
        float ox = __shfl_xor_sync(0xffffffffu, v[r].x, mask);
        float oy = __shfl_xor_sync(0xffffffffu, v[r].y, mask);
        v[r] = cfma2(ca, v[r], cb, make_float2(ox, oy));
    }
}

// outMode: 0 = real-part only (128,1024) f32; 1 = planar re-block then im-block
__global__ __launch_bounds__(THREADS)
void UnitaryR3Ansatz_kernel(const float* __restrict__ inp,
                            const float* __restrict__ params,
                            float* __restrict__ outF,
                            int outMode)
{
    const int b    = blockIdx.x;    // row 0..127
    const int copy = b >> 2;        // jnp.repeat(M, 4)
    const int t    = threadIdx.x;   // 0..255
    const int lane = t & 31;

    __shared__ float2 st[DIM + DIM / 16];       // padded state buffer
    __shared__ float2 mat[LAYERS][NQ][4];       // all rotation matrices

    // --- precompute all 80 rotation matrices (reference _r3 verbatim) ---
    if (t < LAYERS * NQ) {
        const int layer = t / NQ, q = t - layer * NQ;
        const float* a = params + ((size_t)(copy * LAYERS + layer) * NQ + q) * 3;
        const float omega = a[0], theta = a[1], phi = a[2];
        float s,  c;  sincosf(0.5f * theta,         &s,  &c);
        float sp, cp; sincosf(0.5f * (phi + omega), &sp, &cp);
        float sm, cm; sincosf(0.5f * (phi - omega), &sm, &cm);
        mat[layer][q][0] = make_float2( cp * c, -sp * c);   // m11
        mat[layer][q][1] = make_float2(-cm * s, -sm * s);   // m12
        mat[layer][q][2] = make_float2( cm * s, -sm * s);   // m21
        mat[layer][q][3] = make_float2( cp * c,  sp * c);   // m22
    }

    // --- precomputed smem indices ---
    // layout A: j = [warp(3)=j9:7 | lane(5)=j6:2 | reg(2)=j1:0]  ->  j = 4t + r
    // layout B: j = [reg(2)=j9:8 | lane(5)=j7:3 | warp(3)=j2:0]
    int idxB[4];   // B-side linear index (A->B read target == B->A write target)
    int idxE[4];   // entangler gather source for layout-A slot (t, r)
    #pragma unroll
    for (int r = 0; r < 4; ++r) {
        idxB[r] = padi((r << 8) | ((t & 31) << 3) | (t >> 5));
        idxE[r] = padi(sp10((t << 2) | r));
    }

    // --- load input row (layout A, coalesced float4) ---
    const float4 in4 = *(const float4*)(inp + (size_t)b * DIM + (t << 2));
    float2 v[4] = { {in4.x, 0.f}, {in4.y, 0.f}, {in4.z, 0.f}, {in4.w, 0.f} };

    __syncthreads();   // matrices ready

    #pragma unroll 1
    for (int layer = 0; layer < LAYERS; ++layer) {
        const float2* M = &mat[layer][0][0];

        // ===== layout A gates =====
        // qubit 9 (bit 0 = reg bit 0)
        gate_pair(v[0], v[1], M + 9 * 4);
        gate_pair(v[2], v[3], M + 9 * 4);
        // qubit 8 (bit 1 = reg bit 1)
        gate_pair(v[0], v[2], M + 8 * 4);
        gate_pair(v[1], v[3], M + 8 * 4);
        // qubits 7..3 (bits 2..6 = lane bits 0..4)
        #pragma unroll
        for (int p = 2; p <= 6; ++p) {
            const int mask = 1 << (p - 2);
            gate_shfl(v, lane & mask, mask, M + (9 - p) * 4);
        }

        // ===== A -> B remap =====
        __syncthreads();
        #pragma unroll
        for (int r = 0; r < 4; ++r) st[padi((t << 2) | r)] = v[r];
        __syncthreads();
        #pragma unroll
        for (int r = 0; r < 4; ++r) v[r] = st[idxB[r]];

        // ===== layout B gates =====
        // qubit 1 (bit 8 = reg bit 0)
        gate_pair(v[0], v[1], M + 1 * 4);
        gate_pair(v[2], v[3], M + 1 * 4);
        // qubit 0 (bit 9 = reg bit 1)
        gate_pair(v[0], v[2], M + 0 * 4);
        gate_pair(v[1], v[3], M + 0 * 4);
        // qubit 2 (bit 7 = lane bit 4)
        gate_shfl(v, lane & 16, 16, M + 2 * 4);

        // ===== B -> A remap composed with entangler permutation =====
        __syncthreads();
        #pragma unroll
        for (int r = 0; r < 4; ++r) st[idxB[r]] = v[r];
        __syncthreads();
        #pragma unroll
        for (int r = 0; r < 4; ++r) v[r] = st[idxE[r]];
    }

    // --- output (layout A, coalesced float4) ---
    if (outMode == 0) {
        *(float4*)(outF + (size_t)b * DIM + (t << 2)) =
            make_float4(v[0].x, v[1].x, v[2].x, v[3].x);
    } else {
        *(float4*)(outF + (size_t)b * DIM + (t << 2)) =
            make_float4(v[0].x, v[1].x, v[2].x, v[3].x);
        *(float4*)(outF + (size_t)(128 * DIM) + (size_t)b * DIM + (t << 2)) =
            make_float4(v[0].y, v[1].y, v[2].y, v[3].y);
    }
}

extern "C" void kernel_launch(void* const* d_in, const int* in_sizes, int n_in,
                              void* d_out, int out_size)
{
    const float* inp    = (const float*)d_in[0];
    const float* params = (const float*)d_in[1];
    if (n_in >= 2 && in_sizes[0] < in_sizes[1]) {
        inp    = (const float*)d_in[1];
        params = (const float*)d_in[0];
    }
    const int outMode = (out_size == 128 * DIM) ? 0 : 1;

    UnitaryR3Ansatz_kernel<<<128, THREADS>>>(inp, params, (float*)d_out, outMode);
}